// round 1
// baseline (speedup 1.0000x reference)
#include <cuda_runtime.h>
#include <cstdint>

#define NEG_SLOPE 0.01f

static __device__ __forceinline__ float leaky(float x) {
    return x >= 0.0f ? x : NEG_SLOPE * x;
}

// Problem-size constants (fixed by the dataset)
constexpr int NMAX = 100000;

// Scratch (device globals — no allocation allowed)
__device__ float g_H1[(size_t)NMAX * 256];    // H1 then reused as H2
__device__ float g_AGG1[(size_t)NMAX * 256];  // conv1 output (pre-leaky h)
__device__ float g_AGG2[(size_t)NMAX * 256];  // conv2 output (pre-leaky)
__device__ float g_X[(size_t)NMAX * 512];     // concat buffer (X2 then X3)
__device__ int   g_root[NMAX];
__device__ int   g_is64;

// ---------------------------------------------------------------------------
// Index dtype detection: JAX may deliver int64 or (x64-disabled) int32.
// For int64 little-endian values < 2^31, every odd 32-bit word is 0.
// ---------------------------------------------------------------------------
__global__ void detect_k(const void* adjs) {
    const int* a = (const int*)adjs;
    __shared__ int any_nonzero;
    if (threadIdx.x == 0) any_nonzero = 0;
    __syncthreads();
    for (int i = threadIdx.x; i < 1024; i += blockDim.x) {
        if (a[2 * i + 1] != 0) any_nonzero = 1;  // benign race
    }
    __syncthreads();
    if (threadIdx.x == 0) g_is64 = (any_nonzero == 0) ? 1 : 0;
}

static __device__ __forceinline__ int ldidx(const void* p, int i) {
    if (g_is64) return (int)((const long long*)p)[i];
    return ((const int*)p)[i];
}

// ---------------------------------------------------------------------------
// root[i] = root_idx[batch[i]]
// ---------------------------------------------------------------------------
__global__ void root_k(const void* __restrict__ batch,
                       const void* __restrict__ root_idx,
                       int* __restrict__ root, int N) {
    int i = blockIdx.x * blockDim.x + threadIdx.x;
    if (i < N) root[i] = ldidx(root_idx, ldidx(batch, i));
}

// ---------------------------------------------------------------------------
// agg[i, :] = bias[:]
// ---------------------------------------------------------------------------
__global__ void initb_k(float* __restrict__ agg, const float* __restrict__ b, int N) {
    long long idx = (long long)blockIdx.x * blockDim.x + threadIdx.x;
    if (idx >= (long long)N * 64) return;
    int i = (int)(idx >> 6);
    int c = (int)(idx & 63) * 4;
    *(float4*)(agg + (size_t)i * 256 + c) = *(const float4*)(b + c);
}

// ---------------------------------------------------------------------------
// Edge scatter: agg[dst[e], :] += w[e] * H[src[e], :]
// One thread per (edge, float4-column). Vectorized global reduction.
// ---------------------------------------------------------------------------
__global__ void scatter_k(const float* __restrict__ H,
                          const void* __restrict__ adjs, int E,
                          const float* __restrict__ w,
                          float* __restrict__ agg) {
    long long idx = (long long)blockIdx.x * blockDim.x + threadIdx.x;
    if (idx >= (long long)E * 64) return;
    int e  = (int)(idx >> 6);
    int c  = (int)(idx & 63) * 4;
    int s  = ldidx(adjs, e);
    int d  = ldidx(adjs, E + e);
    float wv = __ldg(&w[e]);
    float4 hv = *(const float4*)(H + (size_t)s * 256 + c);
    float* p = agg + (size_t)d * 256 + c;
    asm volatile("red.global.add.v4.f32 [%0], {%1,%2,%3,%4};"
                 :: "l"(p), "f"(wv * hv.x), "f"(wv * hv.y),
                    "f"(wv * hv.z), "f"(wv * hv.w)
                 : "memory");
}

// ---------------------------------------------------------------------------
// Build concat buffer X[N,512]:
//   X[:, 0:256]   = leaky(aggA)
//   X[:, 256:512] = srcB[root]  (leaky applied iff leaky_second)
// ---------------------------------------------------------------------------
__global__ void buildx_k(const float* __restrict__ aggA,
                         const float* __restrict__ srcB,
                         const int* __restrict__ root,
                         float* __restrict__ X, int N, int leaky_second) {
    long long idx = (long long)blockIdx.x * blockDim.x + threadIdx.x;
    if (idx >= (long long)N * 64) return;
    int i = (int)(idx >> 6);
    int c = (int)(idx & 63) * 4;
    float4 a = *(const float4*)(aggA + (size_t)i * 256 + c);
    a.x = leaky(a.x); a.y = leaky(a.y); a.z = leaky(a.z); a.w = leaky(a.w);
    int r = root[i];
    float4 rv = *(const float4*)(srcB + (size_t)r * 256 + c);
    if (leaky_second) {
        rv.x = leaky(rv.x); rv.y = leaky(rv.y); rv.z = leaky(rv.z); rv.w = leaky(rv.w);
    }
    *(float4*)(X + (size_t)i * 512 + c)       = a;
    *(float4*)(X + (size_t)i * 512 + 256 + c) = rv;
}

// ---------------------------------------------------------------------------
// SGEMM: C[M,256] = A[M,K] @ B[K,256]   (fp32, 128x128x8 tiles, 8x8/thread)
// epi=1: C = leaky(C + bias[col])
// ---------------------------------------------------------------------------
__global__ __launch_bounds__(256, 2)
void sgemm_k(const float* __restrict__ A, const float* __restrict__ B,
             float* __restrict__ C, int M, int K,
             const float* __restrict__ bias, int epi) {
    constexpr int BM = 128, BN = 128, BK = 8;
    __shared__ float As[BK][BM];
    __shared__ float Bs[BK][BN];

    const int tid  = threadIdx.x;
    const int bx   = blockIdx.x;  // N tile (0..1)
    const int by   = blockIdx.y;  // M tile
    const int trow = tid >> 4;    // 0..15
    const int tcol = tid & 15;    // 0..15

    float acc[8][8];
#pragma unroll
    for (int i = 0; i < 8; i++)
#pragma unroll
        for (int j = 0; j < 8; j++) acc[i][j] = 0.0f;

    const int a_r = tid >> 1;          // 0..127
    const int a_c = (tid & 1) * 4;     // 0 or 4
    const int b_r = tid >> 5;          // 0..7
    const int b_c = (tid & 31) * 4;    // 0..124

    const int  mrow  = by * BM + a_r;
    const bool avalid = (mrow < M);
    const float* Ap = A + (size_t)mrow * K;
    const float* Bp = B + (size_t)b_r * 256 + bx * BN + b_c;

    for (int k0 = 0; k0 < K; k0 += BK) {
        float4 a4 = avalid ? *(const float4*)(Ap + k0 + a_c)
                           : make_float4(0.f, 0.f, 0.f, 0.f);
        float4 b4 = *(const float4*)(Bp + (size_t)k0 * 256);
        As[a_c + 0][a_r] = a4.x;
        As[a_c + 1][a_r] = a4.y;
        As[a_c + 2][a_r] = a4.z;
        As[a_c + 3][a_r] = a4.w;
        *(float4*)&Bs[b_r][b_c] = b4;
        __syncthreads();

#pragma unroll
        for (int k = 0; k < BK; k++) {
            float ar[8], br[8];
#pragma unroll
            for (int i = 0; i < 8; i++) ar[i] = As[k][trow * 8 + i];
#pragma unroll
            for (int j = 0; j < 8; j++) br[j] = Bs[k][tcol * 8 + j];
#pragma unroll
            for (int i = 0; i < 8; i++)
#pragma unroll
                for (int j = 0; j < 8; j++)
                    acc[i][j] = fmaf(ar[i], br[j], acc[i][j]);
        }
        __syncthreads();
    }

#pragma unroll
    for (int i = 0; i < 8; i++) {
        int row = by * BM + trow * 8 + i;
        if (row >= M) continue;
#pragma unroll
        for (int j = 0; j < 8; j += 4) {
            int col = bx * BN + tcol * 8 + j;
            float4 v = make_float4(acc[i][j], acc[i][j + 1],
                                   acc[i][j + 2], acc[i][j + 3]);
            if (epi) {
                v.x = leaky(v.x + bias[col + 0]);
                v.y = leaky(v.y + bias[col + 1]);
                v.z = leaky(v.z + bias[col + 2]);
                v.w = leaky(v.w + bias[col + 3]);
            }
            *(float4*)(C + (size_t)row * 256 + col) = v;
        }
    }
}

// ---------------------------------------------------------------------------
extern "C" void kernel_launch(void* const* d_in, const int* in_sizes, int n_in,
                              void* d_out, int out_size) {
    const float* features = (const float*)d_in[0];   // [N,256]
    const float* values   = (const float*)d_in[1];   // [E]
    const float* W1       = (const float*)d_in[2];   // [256,256]
    const float* b1       = (const float*)d_in[3];   // [256]
    const float* W2       = (const float*)d_in[4];   // [512,256]
    const float* b2       = (const float*)d_in[5];   // [256]
    const float* Wl       = (const float*)d_in[6];   // [512,256]
    const float* bl       = (const float*)d_in[7];   // [256]
    const void*  adjs     = d_in[8];                 // [2,E] int32/int64
    const void*  batch    = d_in[9];                 // [N]
    const void*  root_idx = d_in[10];                // [B]

    const int N = in_sizes[0] / 256;
    const int E = in_sizes[8] / 2;

    float *H, *AGG1, *AGG2, *X;
    int* root;
    cudaGetSymbolAddress((void**)&H,    g_H1);
    cudaGetSymbolAddress((void**)&AGG1, g_AGG1);
    cudaGetSymbolAddress((void**)&AGG2, g_AGG2);
    cudaGetSymbolAddress((void**)&X,    g_X);
    cudaGetSymbolAddress((void**)&root, g_root);

    float* out = (float*)d_out;

    const int T = 256;
    dim3 gemm_grid(2, (N + 127) / 128);
    long long nwork   = (long long)N * 64;
    long long ework   = (long long)E * 64;
    int nblocks = (int)((nwork + T - 1) / T);
    int eblocks = (int)((ework + T - 1) / T);

    // 0. dtype detection + root gather
    detect_k<<<1, 256>>>(adjs);
    root_k<<<(N + T - 1) / T, T>>>(batch, root_idx, root, N);

    // 1. H1 = features @ W1
    sgemm_k<<<gemm_grid, T>>>(features, W1, H, N, 256, nullptr, 0);

    // 2. AGG1 = b1 + scatter(values * H1[src] -> dst)
    initb_k<<<nblocks, T>>>(AGG1, b1, N);
    scatter_k<<<eblocks, T>>>(H, adjs, E, values, AGG1);

    // 3. X2 = leaky(concat(AGG1, features[root]))
    buildx_k<<<nblocks, T>>>(AGG1, features, root, X, N, 1);

    // 4. H2 = X2 @ W2  (reuse H buffer)
    sgemm_k<<<gemm_grid, T>>>(X, W2, H, N, 512, nullptr, 0);

    // 5. AGG2 = b2 + scatter(values * H2[src] -> dst)
    initb_k<<<nblocks, T>>>(AGG2, b2, N);
    scatter_k<<<eblocks, T>>>(H, adjs, E, values, AGG2);

    // 6. X3 = concat(leaky(AGG2), AGG1[root])   (root2 pre-activation)
    buildx_k<<<nblocks, T>>>(AGG2, AGG1, root, X, N, 0);

    // 7. out = leaky(X3 @ Wl + bl)
    sgemm_k<<<gemm_grid, T>>>(X, Wl, out, N, 512, bl, 1);
}

// round 3
// speedup vs baseline: 2.2379x; 2.2379x over previous
#include <cuda_runtime.h>
#include <cuda_bf16.h>
#include <cstdint>

#define NEG_SLOPE 0.01f

static __device__ __forceinline__ float leaky(float x) {
    return x >= 0.0f ? x : NEG_SLOPE * x;
}

// ---------------------------------------------------------------------------
// Problem-size constants
// ---------------------------------------------------------------------------
constexpr int NMAX = 100000;
constexpr int MPAD_MAX = 100096;          // ceil(100000/128)*128

// Scratch (device globals — no allocation allowed)
__device__ __align__(16) __nv_bfloat16 g_Ahi[(size_t)MPAD_MAX * 512];
__device__ __align__(16) __nv_bfloat16 g_Alo[(size_t)MPAD_MAX * 512];
__device__ __align__(16) __nv_bfloat16 g_Bhi[256 * 512];
__device__ __align__(16) __nv_bfloat16 g_Blo[256 * 512];
__device__ float g_H[(size_t)NMAX * 256];     // GEMM1/GEMM2 output (pre-agg)
__device__ float g_AGG1[(size_t)NMAX * 256];  // conv1 aggregated (pre-leaky)
__device__ float g_AGG2[(size_t)NMAX * 256];  // conv2 aggregated (pre-leaky)
__device__ int   g_root[NMAX];
__device__ int   g_is64;

// ---------------------------------------------------------------------------
// mma.sync / ldmatrix / cp.async primitives (all valid on plain sm_103 target)
// ---------------------------------------------------------------------------
#define LDSM4(r, addr) \
    asm volatile("ldmatrix.sync.aligned.m8n8.x4.shared.b16 {%0,%1,%2,%3}, [%4];" \
        : "=r"((r)[0]), "=r"((r)[1]), "=r"((r)[2]), "=r"((r)[3]) : "r"(addr))

#define MMA_BF16(c, a, b0, b1) \
    asm volatile("mma.sync.aligned.m16n8k16.row.col.f32.bf16.bf16.f32 " \
        "{%0,%1,%2,%3}, {%4,%5,%6,%7}, {%8,%9}, {%0,%1,%2,%3};" \
        : "+f"((c)[0]), "+f"((c)[1]), "+f"((c)[2]), "+f"((c)[3]) \
        : "r"((a)[0]), "r"((a)[1]), "r"((a)[2]), "r"((a)[3]), "r"(b0), "r"(b1))

__device__ __forceinline__ uint32_t smem_to_u32(const void* smem_ptr) {
    uint32_t addr;
    asm("{ .reg .u64 tmp; cvta.to.shared.u64 tmp, %1; cvt.u32.u64 %0, tmp; }"
        : "=r"(addr) : "l"(smem_ptr));
    return addr;
}

__device__ __forceinline__ void cp16(uint32_t dst, const void* src) {
    asm volatile("cp.async.cg.shared.global [%0], [%1], 16;" :: "r"(dst), "l"(src));
}

// ---------------------------------------------------------------------------
// Index dtype detection (JAX may deliver int64 or int32)
// ---------------------------------------------------------------------------
__global__ void detect_k(const void* adjs) {
    const int* a = (const int*)adjs;
    __shared__ int any_nonzero;
    if (threadIdx.x == 0) any_nonzero = 0;
    __syncthreads();
    for (int i = threadIdx.x; i < 1024; i += blockDim.x)
        if (a[2 * i + 1] != 0) any_nonzero = 1;
    __syncthreads();
    if (threadIdx.x == 0) g_is64 = (any_nonzero == 0) ? 1 : 0;
}

static __device__ __forceinline__ int ldidx(const void* p, int i) {
    if (g_is64) return (int)((const long long*)p)[i];
    return ((const int*)p)[i];
}

__global__ void root_k(const void* __restrict__ batch,
                       const void* __restrict__ root_idx,
                       int* __restrict__ root, int N) {
    int i = blockIdx.x * blockDim.x + threadIdx.x;
    if (i < N) root[i] = ldidx(root_idx, ldidx(batch, i));
}

// ---------------------------------------------------------------------------
// agg[i, :] = bias[:]
// ---------------------------------------------------------------------------
__global__ void initb_k(float* __restrict__ agg, const float* __restrict__ b, int N) {
    long long idx = (long long)blockIdx.x * blockDim.x + threadIdx.x;
    if (idx >= (long long)N * 64) return;
    int i = (int)(idx >> 6);
    int c = (int)(idx & 63) * 4;
    *(float4*)(agg + (size_t)i * 256 + c) = *(const float4*)(b + c);
}

// ---------------------------------------------------------------------------
// Edge scatter: agg[dst[e], :] += w[e] * H[src[e], :]
// ---------------------------------------------------------------------------
__global__ void scatter_k(const float* __restrict__ H,
                          const void* __restrict__ adjs, int E,
                          const float* __restrict__ w,
                          float* __restrict__ agg) {
    long long idx = (long long)blockIdx.x * blockDim.x + threadIdx.x;
    if (idx >= (long long)E * 64) return;
    int e  = (int)(idx >> 6);
    int c  = (int)(idx & 63) * 4;
    int s  = ldidx(adjs, e);
    int d  = ldidx(adjs, E + e);
    float wv = __ldg(&w[e]);
    float4 hv = *(const float4*)(H + (size_t)s * 256 + c);
    float* p = agg + (size_t)d * 256 + c;
    asm volatile("red.global.add.v4.f32 [%0], {%1,%2,%3,%4};"
                 :: "l"(p), "f"(wv * hv.x), "f"(wv * hv.y),
                    "f"(wv * hv.z), "f"(wv * hv.w)
                 : "memory");
}

// ---------------------------------------------------------------------------
// bf16 split + pre-swizzled (SW128) GMEM write helper.
// Element (row, k) of a K-wide bf16 matrix lives at byte:
//   row*(K*2) + (k/64)*128 + (((k%64)*2) ^ ((row&7)<<4))
// which reproduces the SMEM SW128 layout when 128 consecutive rows x 64-k
// chunks are copied linearly into a 128B-row SMEM tile.
// ---------------------------------------------------------------------------
static __device__ __forceinline__ void write_split8(
    __nv_bfloat16* __restrict__ Ah, __nv_bfloat16* __restrict__ Al,
    int row, int K, int k0, const float* v) {
    __align__(16) __nv_bfloat16 h[8], l[8];
#pragma unroll
    for (int j = 0; j < 8; j++) {
        float x = v[j];
        __nv_bfloat16 hi = __float2bfloat16(x);
        h[j] = hi;
        l[j] = __float2bfloat16(x - __bfloat162float(hi));
    }
    size_t off = (size_t)row * (K * 2) + ((size_t)(k0 >> 6) << 7)
               + (size_t)(((k0 & 63) * 2) ^ ((row & 7) << 4));
    *(uint4*)((char*)Ah + off) = *(const uint4*)h;
    *(uint4*)((char*)Al + off) = *(const uint4*)l;
}

// features [N, K] fp32 -> split pre-swizzled bf16; zero pad rows [N, Mpad)
__global__ void convA_k(const float* __restrict__ F, int N, int Mpad, int K,
                        __nv_bfloat16* __restrict__ Ah,
                        __nv_bfloat16* __restrict__ Al) {
    long long idx = (long long)blockIdx.x * blockDim.x + threadIdx.x;
    int nk = K >> 3;
    if (idx >= (long long)Mpad * nk) return;
    int row = (int)(idx / nk);
    int k0  = (int)(idx % nk) * 8;
    float v[8];
    if (row < N) {
        float4 a = *(const float4*)(F + (size_t)row * K + k0);
        float4 b = *(const float4*)(F + (size_t)row * K + k0 + 4);
        v[0]=a.x; v[1]=a.y; v[2]=a.z; v[3]=a.w;
        v[4]=b.x; v[5]=b.y; v[6]=b.z; v[7]=b.w;
    } else {
#pragma unroll
        for (int j = 0; j < 8; j++) v[j] = 0.0f;
    }
    write_split8(Ah, Al, row, K, k0, v);
}

// W [K, 256] fp32 -> B[n, k] = W[k, n] split pre-swizzled bf16
__global__ void convW_k(const float* __restrict__ W, int K,
                        __nv_bfloat16* __restrict__ Bh,
                        __nv_bfloat16* __restrict__ Bl) {
    int idx = blockIdx.x * blockDim.x + threadIdx.x;
    int nk = K >> 3;
    if (idx >= 256 * nk) return;
    int n  = idx / nk;
    int k0 = (idx % nk) * 8;
    float v[8];
#pragma unroll
    for (int j = 0; j < 8; j++) v[j] = W[(size_t)(k0 + j) * 256 + n];
    write_split8(Bh, Bl, n, K, k0, v);
}

// X[row, 0:256] = leaky(aggA[row]); X[row, 256:512] = srcB[root[row]] (opt leaky)
// -> split pre-swizzled bf16, K=512; zero pad rows
__global__ void buildx_split_k(const float* __restrict__ aggA,
                               const float* __restrict__ srcB,
                               const int* __restrict__ root,
                               int N, int Mpad,
                               __nv_bfloat16* __restrict__ Ah,
                               __nv_bfloat16* __restrict__ Al,
                               int leaky_second) {
    long long idx = (long long)blockIdx.x * blockDim.x + threadIdx.x;
    if (idx >= (long long)Mpad * 64) return;
    int row = (int)(idx >> 6);
    int k0  = (int)(idx & 63) * 8;
    float v[8];
    if (row < N) {
        const float* src;
        int c;
        bool do_leaky;
        if (k0 < 256) { src = aggA + (size_t)row * 256; c = k0; do_leaky = true; }
        else { src = srcB + (size_t)root[row] * 256; c = k0 - 256; do_leaky = (leaky_second != 0); }
        float4 a = *(const float4*)(src + c);
        float4 b = *(const float4*)(src + c + 4);
        v[0]=a.x; v[1]=a.y; v[2]=a.z; v[3]=a.w;
        v[4]=b.x; v[5]=b.y; v[6]=b.z; v[7]=b.w;
        if (do_leaky) {
#pragma unroll
            for (int j = 0; j < 8; j++) v[j] = leaky(v[j]);
        }
    } else {
#pragma unroll
        for (int j = 0; j < 8; j++) v[j] = 0.0f;
    }
    write_split8(Ah, Al, row, 512, k0, v);
}

// ---------------------------------------------------------------------------
// mma.sync bf16-split GEMM:
//   C[M, 256] = A[M, K] @ W[K, 256]   with A = Ahi+Alo, W^T = Bhi+Blo
// CTA: 512 threads (16 warps), tile 128 x 256, K-chunks of 64, double-buffered
// cp.async. Each warp: 32 x 64 output = 16 m16n8 tiles; 3 mma passes per tile
// (hi*hi + hi*lo + lo*hi), fp32 register accumulation.
// nchunks = K/64.   epi=1: C = leaky(C + bias[col])
// ---------------------------------------------------------------------------
constexpr int GEMM_STAGE_BYTES = 96 * 1024;   // Ah 16K | Al 16K | Bh 32K | Bl 32K
constexpr int GEMM_SMEM = 2 * GEMM_STAGE_BYTES;

__global__ __launch_bounds__(512, 1)
void gemm_tc_k(const __nv_bfloat16* __restrict__ Ahi,
               const __nv_bfloat16* __restrict__ Alo,
               const __nv_bfloat16* __restrict__ Bhi,
               const __nv_bfloat16* __restrict__ Blo,
               float* __restrict__ C, int Mrows, int nchunks,
               const float* __restrict__ bias, int epi) {
    extern __shared__ char smem[];
    const uint32_t smem_base = smem_to_u32(smem);
    const int tid  = threadIdx.x;
    const int wid  = tid >> 5;
    const int lane = tid & 31;
    const int m0   = blockIdx.x * 128;
    const int RB   = nchunks * 128;       // row bytes in GMEM operand matrices

    const int wm32 = (wid & 3) * 32;      // warp row block within tile
    const int wn64 = (wid >> 2) * 64;     // warp col block within tile

    const char* aH = (const char*)Ahi + (size_t)m0 * RB;
    const char* aL = (const char*)Alo + (size_t)m0 * RB;
    const char* bH = (const char*)Bhi;
    const char* bL = (const char*)Blo;

    auto copy_chunk = [&](int chunk, int s) {
        uint32_t sb = smem_base + s * GEMM_STAGE_BYTES;
        size_t co = (size_t)chunk * 128;
        for (int t = tid; t < 1024; t += 512) {          // A hi: 128 rows x 128B
            int r = t >> 3, c = (t & 7) << 4;
            cp16(sb + r * 128 + c, aH + (size_t)r * RB + co + c);
        }
        for (int t = tid; t < 1024; t += 512) {          // A lo
            int r = t >> 3, c = (t & 7) << 4;
            cp16(sb + 16384 + r * 128 + c, aL + (size_t)r * RB + co + c);
        }
        for (int t = tid; t < 2048; t += 512) {          // B hi: 256 rows x 128B
            int r = t >> 3, c = (t & 7) << 4;
            cp16(sb + 32768 + r * 128 + c, bH + (size_t)r * RB + co + c);
        }
        for (int t = tid; t < 2048; t += 512) {          // B lo
            int r = t >> 3, c = (t & 7) << 4;
            cp16(sb + 65536 + r * 128 + c, bL + (size_t)r * RB + co + c);
        }
        asm volatile("cp.async.commit_group;" ::: "memory");
    };

    // Per-thread ldmatrix address constants (SW128 swizzle)
    const int lr = lane & 7;
    const int q  = lane >> 3;
    const uint32_t swz = (uint32_t)(lr << 4);
    const int a_row = wm32 + ((q & 1) << 3) + lr;   // + mt*16
    const int a_kof = (q >> 1) << 3;                // + ks*16
    const int b_row = wn64 + ((q >> 1) << 3) + lr;  // + np*16
    const int b_kof = (q & 1) << 3;                 // + ks*16

    float acc[16][4];
#pragma unroll
    for (int t = 0; t < 16; t++)
#pragma unroll
        for (int j = 0; j < 4; j++) acc[t][j] = 0.0f;

    copy_chunk(0, 0);
    if (nchunks > 1) copy_chunk(1, 1);

    for (int i = 0; i < nchunks; i++) {
        const int s = i & 1;
        if (i + 1 < nchunks) asm volatile("cp.async.wait_group 1;" ::: "memory");
        else                 asm volatile("cp.async.wait_group 0;" ::: "memory");
        __syncthreads();

        const uint32_t sA = smem_base + s * GEMM_STAGE_BYTES;
        const uint32_t sB = sA + 32768;

#pragma unroll
        for (int ks = 0; ks < 4; ks++) {
            uint32_t ah[2][4], al[2][4];
#pragma unroll
            for (int mt = 0; mt < 2; mt++) {
                uint32_t ra = sA + (uint32_t)((a_row + mt * 16) * 128)
                            + ((uint32_t)((a_kof + ks * 16) * 2) ^ swz);
                LDSM4(ah[mt], ra);
                LDSM4(al[mt], ra + 16384);
            }
#pragma unroll
            for (int np = 0; np < 4; np++) {
                uint32_t bh[4], bl2[4];
                uint32_t rb = sB + (uint32_t)((b_row + np * 16) * 128)
                            + ((uint32_t)((b_kof + ks * 16) * 2) ^ swz);
                LDSM4(bh, rb);
                LDSM4(bl2, rb + 32768);
#pragma unroll
                for (int mt = 0; mt < 2; mt++) {
#pragma unroll
                    for (int sub = 0; sub < 2; sub++) {
                        float* c = acc[mt * 8 + np * 2 + sub];
                        MMA_BF16(c, ah[mt], bh[2 * sub], bh[2 * sub + 1]);
                        MMA_BF16(c, ah[mt], bl2[2 * sub], bl2[2 * sub + 1]);
                        MMA_BF16(c, al[mt], bh[2 * sub], bh[2 * sub + 1]);
                    }
                }
            }
        }
        __syncthreads();               // all warps done reading stage s
        if (i + 2 < nchunks) copy_chunk(i + 2, s);
    }

    // Epilogue: registers -> C, optional bias + leaky
    const int gr = lane >> 2;
    const int gc = (lane & 3) * 2;
#pragma unroll
    for (int mt = 0; mt < 2; mt++) {
#pragma unroll
        for (int np = 0; np < 4; np++) {
#pragma unroll
            for (int sub = 0; sub < 2; sub++) {
                const float* c = acc[mt * 8 + np * 2 + sub];
                int col  = wn64 + np * 16 + sub * 8 + gc;
                int row0 = m0 + wm32 + mt * 16 + gr;
                float b0 = 0.f, b1 = 0.f;
                if (epi) { b0 = bias[col]; b1 = bias[col + 1]; }
                if (row0 < Mrows) {
                    float2 v = make_float2(c[0], c[1]);
                    if (epi) { v.x = leaky(v.x + b0); v.y = leaky(v.y + b1); }
                    *(float2*)(C + (size_t)row0 * 256 + col) = v;
                }
                if (row0 + 8 < Mrows) {
                    float2 v = make_float2(c[2], c[3]);
                    if (epi) { v.x = leaky(v.x + b0); v.y = leaky(v.y + b1); }
                    *(float2*)(C + (size_t)(row0 + 8) * 256 + col) = v;
                }
            }
        }
    }
}

// ---------------------------------------------------------------------------
extern "C" void kernel_launch(void* const* d_in, const int* in_sizes, int n_in,
                              void* d_out, int out_size) {
    const float* features = (const float*)d_in[0];   // [N,256]
    const float* values   = (const float*)d_in[1];   // [E]
    const float* W1       = (const float*)d_in[2];   // [256,256]
    const float* b1       = (const float*)d_in[3];   // [256]
    const float* W2       = (const float*)d_in[4];   // [512,256]
    const float* b2       = (const float*)d_in[5];   // [256]
    const float* Wl       = (const float*)d_in[6];   // [512,256]
    const float* bl       = (const float*)d_in[7];   // [256]
    const void*  adjs     = d_in[8];                 // [2,E]
    const void*  batch    = d_in[9];                 // [N]
    const void*  root_idx = d_in[10];                // [B]

    const int N = in_sizes[0] / 256;
    const int E = in_sizes[8] / 2;
    const int ntiles = (N + 127) / 128;
    const int Mpad = ntiles * 128;

    __nv_bfloat16 *Ah, *Al, *Bh, *Bl;
    float *H, *AGG1, *AGG2;
    int* root;
    cudaGetSymbolAddress((void**)&Ah,   g_Ahi);
    cudaGetSymbolAddress((void**)&Al,   g_Alo);
    cudaGetSymbolAddress((void**)&Bh,   g_Bhi);
    cudaGetSymbolAddress((void**)&Bl,   g_Blo);
    cudaGetSymbolAddress((void**)&H,    g_H);
    cudaGetSymbolAddress((void**)&AGG1, g_AGG1);
    cudaGetSymbolAddress((void**)&AGG2, g_AGG2);
    cudaGetSymbolAddress((void**)&root, g_root);

    cudaFuncSetAttribute(gemm_tc_k, cudaFuncAttributeMaxDynamicSharedMemorySize, GEMM_SMEM);

    float* out = (float*)d_out;
    const int T = 256;
    long long nwork = (long long)N * 64;
    long long ework = (long long)E * 64;
    int nblocks = (int)((nwork + T - 1) / T);
    int eblocks = (int)((ework + T - 1) / T);
    int convA_blocks  = (int)(((long long)Mpad * 32 + T - 1) / T);
    int buildx_blocks = (int)(((long long)Mpad * 64 + T - 1) / T);

    // 0. dtype detection + root gather
    detect_k<<<1, 256>>>(adjs);
    root_k<<<(N + T - 1) / T, T>>>(batch, root_idx, root, N);

    // 1. H1 = features @ W1 (bf16-split mma.sync, K=256 -> 4 chunks)
    convW_k<<<(256 * 32 + T - 1) / T, T>>>(W1, 256, Bh, Bl);
    convA_k<<<convA_blocks, T>>>(features, N, Mpad, 256, Ah, Al);
    gemm_tc_k<<<ntiles, 512, GEMM_SMEM>>>(Ah, Al, Bh, Bl, H, N, 4, nullptr, 0);

    // 2. AGG1 = b1 + scatter(values * H1[src] -> dst)
    initb_k<<<nblocks, T>>>(AGG1, b1, N);
    scatter_k<<<eblocks, T>>>(H, adjs, E, values, AGG1);

    // 3. X2 = leaky(concat(AGG1, features[root])) -> split bf16 (K=512)
    buildx_split_k<<<buildx_blocks, T>>>(AGG1, features, root, N, Mpad, Ah, Al, 1);

    // 4. H2 = X2 @ W2 (K=512 -> 8 chunks)
    convW_k<<<(256 * 64 + T - 1) / T, T>>>(W2, 512, Bh, Bl);
    gemm_tc_k<<<ntiles, 512, GEMM_SMEM>>>(Ah, Al, Bh, Bl, H, N, 8, nullptr, 0);

    // 5. AGG2 = b2 + scatter(values * H2[src] -> dst)
    initb_k<<<nblocks, T>>>(AGG2, b2, N);
    scatter_k<<<eblocks, T>>>(H, adjs, E, values, AGG2);

    // 6. X3 = concat(leaky(AGG2), AGG1[root]) -> split bf16 (K=512)
    buildx_split_k<<<buildx_blocks, T>>>(AGG2, AGG1, root, N, Mpad, Ah, Al, 0);

    // 7. out = leaky(X3 @ Wl + bl)
    convW_k<<<(256 * 64 + T - 1) / T, T>>>(Wl, 512, Bh, Bl);
    gemm_tc_k<<<ntiles, 512, GEMM_SMEM>>>(Ah, Al, Bh, Bl, out, N, 8, bl, 1);
}

// round 5
// speedup vs baseline: 2.6513x; 1.1847x over previous
#include <cuda_runtime.h>
#include <cuda_bf16.h>
#include <cstdint>

#define NEG_SLOPE 0.01f

static __device__ __forceinline__ float leaky(float x) {
    return x >= 0.0f ? x : NEG_SLOPE * x;
}

// ---------------------------------------------------------------------------
// Problem-size constants
// ---------------------------------------------------------------------------
constexpr int NMAX = 100000;
constexpr int MPAD_MAX = 100096;          // ceil(100000/128)*128
constexpr int BMAX = 128;                 // batch count (one GEMM tile)

// Scratch (device globals — no allocation allowed). All GEMM K = 256 now.
__device__ __align__(16) __nv_bfloat16 g_Ahi[(size_t)MPAD_MAX * 256];
__device__ __align__(16) __nv_bfloat16 g_Alo[(size_t)MPAD_MAX * 256];
__device__ __align__(16) __nv_bfloat16 g_Bhi[256 * 256];   // W_top, B layout
__device__ __align__(16) __nv_bfloat16 g_Blo[256 * 256];
__device__ __align__(16) __nv_bfloat16 g_B2hi[256 * 256];  // W_bot, B layout
__device__ __align__(16) __nv_bfloat16 g_B2lo[256 * 256];
__device__ __align__(16) __nv_bfloat16 g_RAhi[BMAX * 256]; // root-rows A
__device__ __align__(16) __nv_bfloat16 g_RAlo[BMAX * 256];
__device__ float g_R[BMAX * 256];             // root-term GEMM result
__device__ float g_H[(size_t)NMAX * 256];     // GEMM1/GEMM2 output (pre-agg)
__device__ float g_AGG1[(size_t)NMAX * 256];  // conv1 aggregated (pre-leaky)
__device__ float g_AGG2[(size_t)NMAX * 256];  // conv2 aggregated (pre-leaky)
__device__ int   g_root[NMAX];
__device__ int   g_batch32[NMAX];
__device__ int   g_is64;

// ---------------------------------------------------------------------------
// mma.sync / ldmatrix / cp.async primitives (valid on plain sm_103 target)
// ---------------------------------------------------------------------------
#define LDSM4(r, addr) \
    asm volatile("ldmatrix.sync.aligned.m8n8.x4.shared.b16 {%0,%1,%2,%3}, [%4];" \
        : "=r"((r)[0]), "=r"((r)[1]), "=r"((r)[2]), "=r"((r)[3]) : "r"(addr))

#define MMA_BF16(c, a, b0, b1) \
    asm volatile("mma.sync.aligned.m16n8k16.row.col.f32.bf16.bf16.f32 " \
        "{%0,%1,%2,%3}, {%4,%5,%6,%7}, {%8,%9}, {%0,%1,%2,%3};" \
        : "+f"((c)[0]), "+f"((c)[1]), "+f"((c)[2]), "+f"((c)[3]) \
        : "r"((a)[0]), "r"((a)[1]), "r"((a)[2]), "r"((a)[3]), "r"(b0), "r"(b1))

__device__ __forceinline__ uint32_t smem_to_u32(const void* smem_ptr) {
    uint32_t addr;
    asm("{ .reg .u64 tmp; cvta.to.shared.u64 tmp, %1; cvt.u32.u64 %0, tmp; }"
        : "=r"(addr) : "l"(smem_ptr));
    return addr;
}

__device__ __forceinline__ void cp16(uint32_t dst, const void* src) {
    asm volatile("cp.async.cg.shared.global [%0], [%1], 16;" :: "r"(dst), "l"(src));
}

// ---------------------------------------------------------------------------
// Index dtype detection (JAX may deliver int64 or int32)
// ---------------------------------------------------------------------------
__global__ void detect_k(const void* adjs) {
    const int* a = (const int*)adjs;
    __shared__ int any_nonzero;
    if (threadIdx.x == 0) any_nonzero = 0;
    __syncthreads();
    for (int i = threadIdx.x; i < 1024; i += blockDim.x)
        if (a[2 * i + 1] != 0) any_nonzero = 1;
    __syncthreads();
    if (threadIdx.x == 0) g_is64 = (any_nonzero == 0) ? 1 : 0;
}

static __device__ __forceinline__ int ldidx(const void* p, int i) {
    if (g_is64) return (int)((const long long*)p)[i];
    return ((const int*)p)[i];
}

// root[i] = root_idx[batch[i]];  batch32[i] = (int)batch[i]
__global__ void root_k(const void* __restrict__ batch,
                       const void* __restrict__ root_idx,
                       int* __restrict__ root, int* __restrict__ batch32, int N) {
    int i = blockIdx.x * blockDim.x + threadIdx.x;
    if (i < N) {
        int b = ldidx(batch, i);
        batch32[i] = b;
        root[i] = ldidx(root_idx, b);
    }
}

// ---------------------------------------------------------------------------
// agg[i, :] = bias[:]
// ---------------------------------------------------------------------------
__global__ void initb_k(float* __restrict__ agg, const float* __restrict__ b, int N) {
    long long idx = (long long)blockIdx.x * blockDim.x + threadIdx.x;
    if (idx >= (long long)N * 64) return;
    int i = (int)(idx >> 6);
    int c = (int)(idx & 63) * 4;
    *(float4*)(agg + (size_t)i * 256 + c) = *(const float4*)(b + c);
}

// ---------------------------------------------------------------------------
// Edge scatter: agg[dst[e], :] += w[e] * H[src[e], :]
// ---------------------------------------------------------------------------
__global__ void scatter_k(const float* __restrict__ H,
                          const void* __restrict__ adjs, int E,
                          const float* __restrict__ w,
                          float* __restrict__ agg) {
    long long idx = (long long)blockIdx.x * blockDim.x + threadIdx.x;
    if (idx >= (long long)E * 64) return;
    int e  = (int)(idx >> 6);
    int c  = (int)(idx & 63) * 4;
    int s  = ldidx(adjs, e);
    int d  = ldidx(adjs, E + e);
    float wv = __ldg(&w[e]);
    float4 hv = *(const float4*)(H + (size_t)s * 256 + c);
    float* p = agg + (size_t)d * 256 + c;
    asm volatile("red.global.add.v4.f32 [%0], {%1,%2,%3,%4};"
                 :: "l"(p), "f"(wv * hv.x), "f"(wv * hv.y),
                    "f"(wv * hv.z), "f"(wv * hv.w)
                 : "memory");
}

// ---------------------------------------------------------------------------
// bf16 split + pre-swizzled (SW128) GMEM write helper, K=256 layout.
// Element (row, k) lives at byte:
//   row*512 + (k/64)*128 + (((k%64)*2) ^ ((row&7)<<4))
// ---------------------------------------------------------------------------
static __device__ __forceinline__ void write_split8(
    __nv_bfloat16* __restrict__ Ah, __nv_bfloat16* __restrict__ Al,
    int row, int k0, const float* v) {
    __align__(16) __nv_bfloat16 h[8], l[8];
#pragma unroll
    for (int j = 0; j < 8; j++) {
        float x = v[j];
        __nv_bfloat16 hi = __float2bfloat16(x);
        h[j] = hi;
        l[j] = __float2bfloat16(x - __bfloat162float(hi));
    }
    size_t off = (size_t)row * 512 + ((size_t)(k0 >> 6) << 7)
               + (size_t)(((k0 & 63) * 2) ^ ((row & 7) << 4));
    *(uint4*)((char*)Ah + off) = *(const uint4*)h;
    *(uint4*)((char*)Al + off) = *(const uint4*)l;
}

// src [N, 256] fp32 -> split pre-swizzled bf16 (optional leaky); zero pad rows
__global__ void convA_k(const float* __restrict__ F, int N, int Mpad, int do_leaky,
                        __nv_bfloat16* __restrict__ Ah,
                        __nv_bfloat16* __restrict__ Al) {
    long long idx = (long long)blockIdx.x * blockDim.x + threadIdx.x;
    if (idx >= (long long)Mpad * 32) return;
    int row = (int)(idx >> 5);
    int k0  = (int)(idx & 31) * 8;
    float v[8];
    if (row < N) {
        float4 a = *(const float4*)(F + (size_t)row * 256 + k0);
        float4 b = *(const float4*)(F + (size_t)row * 256 + k0 + 4);
        v[0]=a.x; v[1]=a.y; v[2]=a.z; v[3]=a.w;
        v[4]=b.x; v[5]=b.y; v[6]=b.z; v[7]=b.w;
        if (do_leaky) {
#pragma unroll
            for (int j = 0; j < 8; j++) v[j] = leaky(v[j]);
        }
    } else {
#pragma unroll
        for (int j = 0; j < 8; j++) v[j] = 0.0f;
    }
    write_split8(Ah, Al, row, k0, v);
}

// W slice [off:off+256, 256] fp32 -> B[n, k] = W[off+k, n] split pre-swizzled
__global__ void convW_k(const float* __restrict__ W, int off,
                        __nv_bfloat16* __restrict__ Bh,
                        __nv_bfloat16* __restrict__ Bl) {
    int idx = blockIdx.x * blockDim.x + threadIdx.x;
    if (idx >= 256 * 32) return;
    int n  = idx >> 5;
    int k0 = (idx & 31) * 8;
    float v[8];
#pragma unroll
    for (int j = 0; j < 8; j++) v[j] = W[(size_t)(off + k0 + j) * 256 + n];
    write_split8(Bh, Bl, n, k0, v);
}

// RA[b, :] = (leaky?) src[root_idx[b], :]  -> split pre-swizzled; pad b>=B zero
__global__ void convroot_k(const float* __restrict__ src,
                           const void* __restrict__ root_idx, int B, int do_leaky,
                           __nv_bfloat16* __restrict__ RAh,
                           __nv_bfloat16* __restrict__ RAl) {
    int idx = blockIdx.x * blockDim.x + threadIdx.x;
    if (idx >= BMAX * 32) return;
    int b  = idx >> 5;
    int k0 = (idx & 31) * 8;
    float v[8];
    if (b < B) {
        int r = ldidx(root_idx, b);
        float4 a = *(const float4*)(src + (size_t)r * 256 + k0);
        float4 c = *(const float4*)(src + (size_t)r * 256 + k0 + 4);
        v[0]=a.x; v[1]=a.y; v[2]=a.z; v[3]=a.w;
        v[4]=c.x; v[5]=c.y; v[6]=c.z; v[7]=c.w;
        if (do_leaky) {
#pragma unroll
            for (int j = 0; j < 8; j++) v[j] = leaky(v[j]);
        }
    } else {
#pragma unroll
        for (int j = 0; j < 8; j++) v[j] = 0.0f;
    }
    write_split8(RAh, RAl, b, k0, v);
}

// ---------------------------------------------------------------------------
// mma.sync bf16-split GEMM, K = 256 (4 chunks of 64):
//   C[M, 256] = A[M, 256] @ W[256, 256]  (A = Ahi+Alo, W^T = Bhi+Blo)
// CTA: 512 threads (16 warps), tile 128 x 256, double-buffered cp.async.
// 3 mma passes per tile (hi*hi + hi*lo + lo*hi), fp32 register accumulation.
// Epilogue: C = acc (+ Radd[bmap[row]]) (+bias, leaky if epi).
// ---------------------------------------------------------------------------
constexpr int GEMM_STAGE_BYTES = 96 * 1024;   // Ah 16K | Al 16K | Bh 32K | Bl 32K
constexpr int GEMM_SMEM = 2 * GEMM_STAGE_BYTES;
constexpr int NCHUNKS = 4;
constexpr int RB = 512;   // row bytes of K=256 bf16 operand

__global__ __launch_bounds__(512, 1)
void gemm_tc_k(const __nv_bfloat16* __restrict__ Ahi,
               const __nv_bfloat16* __restrict__ Alo,
               const __nv_bfloat16* __restrict__ Bhi,
               const __nv_bfloat16* __restrict__ Blo,
               float* __restrict__ C, int Mrows,
               const float* __restrict__ Radd, const int* __restrict__ bmap,
               const float* __restrict__ bias, int epi) {
    extern __shared__ char smem[];
    const uint32_t smem_base = smem_to_u32(smem);
    const int tid  = threadIdx.x;
    const int wid  = tid >> 5;
    const int lane = tid & 31;
    const int m0   = blockIdx.x * 128;

    const int wm32 = (wid & 3) * 32;      // warp row block within tile
    const int wn64 = (wid >> 2) * 64;     // warp col block within tile

    const char* aH = (const char*)Ahi + (size_t)m0 * RB;
    const char* aL = (const char*)Alo + (size_t)m0 * RB;
    const char* bH = (const char*)Bhi;
    const char* bL = (const char*)Blo;

    auto copy_chunk = [&](int chunk, int s) {
        uint32_t sb = smem_base + s * GEMM_STAGE_BYTES;
        size_t co = (size_t)chunk * 128;
        for (int t = tid; t < 1024; t += 512) {          // A hi: 128 rows x 128B
            int r = t >> 3, c = (t & 7) << 4;
            cp16(sb + r * 128 + c, aH + (size_t)r * RB + co + c);
        }
        for (int t = tid; t < 1024; t += 512) {          // A lo
            int r = t >> 3, c = (t & 7) << 4;
            cp16(sb + 16384 + r * 128 + c, aL + (size_t)r * RB + co + c);
        }
        for (int t = tid; t < 2048; t += 512) {          // B hi: 256 rows x 128B
            int r = t >> 3, c = (t & 7) << 4;
            cp16(sb + 32768 + r * 128 + c, bH + (size_t)r * RB + co + c);
        }
        for (int t = tid; t < 2048; t += 512) {          // B lo
            int r = t >> 3, c = (t & 7) << 4;
            cp16(sb + 65536 + r * 128 + c, bL + (size_t)r * RB + co + c);
        }
        asm volatile("cp.async.commit_group;" ::: "memory");
    };

    // Per-thread ldmatrix address constants (SW128 swizzle)
    const int lr = lane & 7;
    const int q  = lane >> 3;
    const uint32_t swz = (uint32_t)(lr << 4);
    const int a_row = wm32 + ((q & 1) << 3) + lr;   // + mt*16
    const int a_kof = (q >> 1) << 3;                // + ks*16
    const int b_row = wn64 + ((q >> 1) << 3) + lr;  // + np*16
    const int b_kof = (q & 1) << 3;                 // + ks*16

    float acc[16][4];
#pragma unroll
    for (int t = 0; t < 16; t++)
#pragma unroll
        for (int j = 0; j < 4; j++) acc[t][j] = 0.0f;

    copy_chunk(0, 0);
    copy_chunk(1, 1);

    for (int i = 0; i < NCHUNKS; i++) {
        const int s = i & 1;
        if (i + 1 < NCHUNKS) asm volatile("cp.async.wait_group 1;" ::: "memory");
        else                 asm volatile("cp.async.wait_group 0;" ::: "memory");
        __syncthreads();

        const uint32_t sA = smem_base + s * GEMM_STAGE_BYTES;
        const uint32_t sB = sA + 32768;

#pragma unroll
        for (int ks = 0; ks < 4; ks++) {
            uint32_t ah[2][4], al[2][4];
#pragma unroll
            for (int mt = 0; mt < 2; mt++) {
                uint32_t ra = sA + (uint32_t)((a_row + mt * 16) * 128)
                            + ((uint32_t)((a_kof + ks * 16) * 2) ^ swz);
                LDSM4(ah[mt], ra);
                LDSM4(al[mt], ra + 16384);
            }
#pragma unroll
            for (int np = 0; np < 4; np++) {
                uint32_t bh[4], bl2[4];
                uint32_t rb = sB + (uint32_t)((b_row + np * 16) * 128)
                            + ((uint32_t)((b_kof + ks * 16) * 2) ^ swz);
                LDSM4(bh, rb);
                LDSM4(bl2, rb + 32768);
#pragma unroll
                for (int mt = 0; mt < 2; mt++) {
#pragma unroll
                    for (int sub = 0; sub < 2; sub++) {
                        float* c = acc[mt * 8 + np * 2 + sub];
                        MMA_BF16(c, ah[mt], bh[2 * sub], bh[2 * sub + 1]);
                        MMA_BF16(c, ah[mt], bl2[2 * sub], bl2[2 * sub + 1]);
                        MMA_BF16(c, al[mt], bh[2 * sub], bh[2 * sub + 1]);
                    }
                }
            }
        }
        __syncthreads();               // all warps done reading stage s
        if (i + 2 < NCHUNKS) copy_chunk(i + 2, s);
    }

    // Epilogue: registers -> C, optional root-term add + bias + leaky
    const int gr = lane >> 2;
    const int gc = (lane & 3) * 2;
#pragma unroll
    for (int mt = 0; mt < 2; mt++) {
        int row0 = m0 + wm32 + mt * 16 + gr;
        int row8 = row0 + 8;
        const float* R0 = nullptr;
        const float* R8 = nullptr;
        if (Radd) {
            if (row0 < Mrows) R0 = Radd + (size_t)bmap[row0] * 256;
            if (row8 < Mrows) R8 = Radd + (size_t)bmap[row8] * 256;
        }
#pragma unroll
        for (int np = 0; np < 4; np++) {
#pragma unroll
            for (int sub = 0; sub < 2; sub++) {
                const float* c = acc[mt * 8 + np * 2 + sub];
                int col = wn64 + np * 16 + sub * 8 + gc;
                float b0 = 0.f, b1 = 0.f;
                if (epi) { b0 = bias[col]; b1 = bias[col + 1]; }
                if (row0 < Mrows) {
                    float2 v = make_float2(c[0], c[1]);
                    if (R0) { v.x += R0[col]; v.y += R0[col + 1]; }
                    if (epi) { v.x = leaky(v.x + b0); v.y = leaky(v.y + b1); }
                    *(float2*)(C + (size_t)row0 * 256 + col) = v;
                }
                if (row8 < Mrows) {
                    float2 v = make_float2(c[2], c[3]);
                    if (R8) { v.x += R8[col]; v.y += R8[col + 1]; }
                    if (epi) { v.x = leaky(v.x + b0); v.y = leaky(v.y + b1); }
                    *(float2*)(C + (size_t)row8 * 256 + col) = v;
                }
            }
        }
    }
}

// ---------------------------------------------------------------------------
extern "C" void kernel_launch(void* const* d_in, const int* in_sizes, int n_in,
                              void* d_out, int out_size) {
    const float* features = (const float*)d_in[0];   // [N,256]
    const float* values   = (const float*)d_in[1];   // [E]
    const float* W1       = (const float*)d_in[2];   // [256,256]
    const float* b1       = (const float*)d_in[3];   // [256]
    const float* W2       = (const float*)d_in[4];   // [512,256]
    const float* b2       = (const float*)d_in[5];   // [256]
    const float* Wl       = (const float*)d_in[6];   // [512,256]
    const float* bl       = (const float*)d_in[7];   // [256]
    const void*  adjs     = d_in[8];                 // [2,E]
    const void*  batch    = d_in[9];                 // [N]
    const void*  root_idx = d_in[10];                // [B]

    const int N = in_sizes[0] / 256;
    const int E = in_sizes[8] / 2;
    const int B = in_sizes[10];
    const int ntiles = (N + 127) / 128;
    const int Mpad = ntiles * 128;

    __nv_bfloat16 *Ah, *Al, *Bh, *Bl, *B2h, *B2l, *RAh, *RAl;
    float *H, *AGG1, *AGG2, *R;
    int *root, *batch32;
    cudaGetSymbolAddress((void**)&Ah,     g_Ahi);
    cudaGetSymbolAddress((void**)&Al,     g_Alo);
    cudaGetSymbolAddress((void**)&Bh,     g_Bhi);
    cudaGetSymbolAddress((void**)&Bl,     g_Blo);
    cudaGetSymbolAddress((void**)&B2h,    g_B2hi);
    cudaGetSymbolAddress((void**)&B2l,    g_B2lo);
    cudaGetSymbolAddress((void**)&RAh,    g_RAhi);
    cudaGetSymbolAddress((void**)&RAl,    g_RAlo);
    cudaGetSymbolAddress((void**)&R,      g_R);
    cudaGetSymbolAddress((void**)&H,      g_H);
    cudaGetSymbolAddress((void**)&AGG1,   g_AGG1);
    cudaGetSymbolAddress((void**)&AGG2,   g_AGG2);
    cudaGetSymbolAddress((void**)&root,   g_root);
    cudaGetSymbolAddress((void**)&batch32,g_batch32);

    cudaFuncSetAttribute(gemm_tc_k, cudaFuncAttributeMaxDynamicSharedMemorySize, GEMM_SMEM);

    float* out = (float*)d_out;
    const int T = 256;
    long long nwork = (long long)N * 64;
    long long ework = (long long)E * 64;
    int nblocks = (int)((nwork + T - 1) / T);
    int eblocks = (int)((ework + T - 1) / T);
    int convA_blocks = (int)(((long long)Mpad * 32 + T - 1) / T);
    int convW_blocks = (256 * 32 + T - 1) / T;
    int convR_blocks = (BMAX * 32 + T - 1) / T;

    // launch index:                                              (ncu -s 5 slot)
    detect_k<<<1, 256>>>(adjs);                                         // 0
    root_k<<<(N + T - 1) / T, T>>>(batch, root_idx, root, batch32, N);  // 1

    // --- conv1: H1 = features @ W1 ---
    convW_k<<<convW_blocks, T>>>(W1, 0, Bh, Bl);                        // 2
    convA_k<<<convA_blocks, T>>>(features, N, Mpad, 0, Ah, Al);         // 3
    initb_k<<<nblocks, T>>>(AGG1, b1, N);                               // 4
    gemm_tc_k<<<ntiles, 512, GEMM_SMEM>>>(Ah, Al, Bh, Bl, H, N,
                                          nullptr, nullptr, nullptr, 0); // 5 <- ncu
    scatter_k<<<eblocks, T>>>(H, adjs, E, values, AGG1);                // 6

    // --- conv2: H2 = leaky(AGG1) @ W2_top + leaky(f1[root]) @ W2_bot ---
    convW_k<<<convW_blocks, T>>>(W2, 0, Bh, Bl);
    convW_k<<<convW_blocks, T>>>(W2, 256, B2h, B2l);
    convroot_k<<<convR_blocks, T>>>(features, root_idx, B, 1, RAh, RAl);
    gemm_tc_k<<<1, 512, GEMM_SMEM>>>(RAh, RAl, B2h, B2l, R, B,
                                     nullptr, nullptr, nullptr, 0);
    convA_k<<<convA_blocks, T>>>(AGG1, N, Mpad, 1, Ah, Al);
    gemm_tc_k<<<ntiles, 512, GEMM_SMEM>>>(Ah, Al, Bh, Bl, H, N,
                                          R, batch32, nullptr, 0);
    initb_k<<<nblocks, T>>>(AGG2, b2, N);
    scatter_k<<<eblocks, T>>>(H, adjs, E, values, AGG2);

    // --- final: out = leaky(leaky(AGG2) @ Wl_top + AGG1[root] @ Wl_bot + bl) ---
    convW_k<<<convW_blocks, T>>>(Wl, 0, Bh, Bl);
    convW_k<<<convW_blocks, T>>>(Wl, 256, B2h, B2l);
    convroot_k<<<convR_blocks, T>>>(AGG1, root_idx, B, 0, RAh, RAl);
    gemm_tc_k<<<1, 512, GEMM_SMEM>>>(RAh, RAl, B2h, B2l, R, B,
                                     nullptr, nullptr, nullptr, 0);
    convA_k<<<convA_blocks, T>>>(AGG2, N, Mpad, 1, Ah, Al);
    gemm_tc_k<<<ntiles, 512, GEMM_SMEM>>>(Ah, Al, Bh, Bl, out, N,
                                          R, batch32, bl, 1);
}

// round 7
// speedup vs baseline: 2.7963x; 1.0547x over previous
#include <cuda_runtime.h>
#include <cuda_bf16.h>
#include <cstdint>

#define NEG_SLOPE 0.01f

static __device__ __forceinline__ float leaky(float x) {
    return x >= 0.0f ? x : NEG_SLOPE * x;
}

// ---------------------------------------------------------------------------
// Problem-size constants
// ---------------------------------------------------------------------------
constexpr int NMAX = 100000;
constexpr int BMAX = 128;                 // batch count (one GEMM tile of rows)

// Scratch (device globals — no allocation allowed)
__device__ __align__(16) __nv_bfloat16 g_Bhi[256 * 256];   // W_top split (B layout)
__device__ __align__(16) __nv_bfloat16 g_Blo[256 * 256];
__device__ __align__(16) __nv_bfloat16 g_B2hi[256 * 256];  // W_bot split
__device__ __align__(16) __nv_bfloat16 g_B2lo[256 * 256];
__device__ float g_R[BMAX * 256];             // root-term GEMM result
__device__ float g_H[(size_t)NMAX * 256];     // GEMM1/GEMM2 output (pre-agg)
__device__ float g_AGG1[(size_t)NMAX * 256];  // conv1 aggregated
__device__ float g_AGG2[(size_t)NMAX * 256];  // conv2 aggregated
__device__ int   g_batch32[NMAX];
__device__ int   g_rootidx32[BMAX];
__device__ int   g_is64;

// ---------------------------------------------------------------------------
// mma.sync / ldmatrix / cp.async primitives (valid on plain sm_103 target)
// ---------------------------------------------------------------------------
#define LDSM4(r, addr) \
    asm volatile("ldmatrix.sync.aligned.m8n8.x4.shared.b16 {%0,%1,%2,%3}, [%4];" \
        : "=r"((r)[0]), "=r"((r)[1]), "=r"((r)[2]), "=r"((r)[3]) : "r"(addr))

#define MMA_BF16(c, a, b0, b1) \
    asm volatile("mma.sync.aligned.m16n8k16.row.col.f32.bf16.bf16.f32 " \
        "{%0,%1,%2,%3}, {%4,%5,%6,%7}, {%8,%9}, {%0,%1,%2,%3};" \
        : "+f"((c)[0]), "+f"((c)[1]), "+f"((c)[2]), "+f"((c)[3]) \
        : "r"((a)[0]), "r"((a)[1]), "r"((a)[2]), "r"((a)[3]), "r"(b0), "r"(b1))

__device__ __forceinline__ uint32_t smem_to_u32(const void* smem_ptr) {
    uint32_t addr;
    asm("{ .reg .u64 tmp; cvta.to.shared.u64 tmp, %1; cvt.u32.u64 %0, tmp; }"
        : "=r"(addr) : "l"(smem_ptr));
    return addr;
}

__device__ __forceinline__ void cp16(uint32_t dst, const void* src) {
    asm volatile("cp.async.cg.shared.global [%0], [%1], 16;" :: "r"(dst), "l"(src));
}

// Zero-fill variant: src-size 0 writes zeros (used for tail rows)
__device__ __forceinline__ void cp16z(uint32_t dst, const void* src, bool ok) {
    int sz = ok ? 16 : 0;
    asm volatile("cp.async.cg.shared.global [%0], [%1], 16, %2;"
                 :: "r"(dst), "l"(src), "r"(sz));
}

// ---------------------------------------------------------------------------
// Index dtype detection (JAX may deliver int64 or int32)
// ---------------------------------------------------------------------------
__global__ void detect_k(const void* adjs) {
    const int* a = (const int*)adjs;
    __shared__ int any_nonzero;
    if (threadIdx.x == 0) any_nonzero = 0;
    __syncthreads();
    for (int i = threadIdx.x; i < 1024; i += blockDim.x)
        if (a[2 * i + 1] != 0) any_nonzero = 1;
    __syncthreads();
    if (threadIdx.x == 0) g_is64 = (any_nonzero == 0) ? 1 : 0;
}

static __device__ __forceinline__ int ldidx(const void* p, int i) {
    if (g_is64) return (int)((const long long*)p)[i];
    return ((const int*)p)[i];
}

// batch32[i] = (int)batch[i];  rootidx32[b] = (int)root_idx[b] (padded 0)
__global__ void root_k(const void* __restrict__ batch,
                       const void* __restrict__ root_idx,
                       int* __restrict__ batch32, int* __restrict__ rootidx32,
                       int N, int B) {
    int i = blockIdx.x * blockDim.x + threadIdx.x;
    if (i < N) batch32[i] = ldidx(batch, i);
    if (i < BMAX) rootidx32[i] = (i < B) ? ldidx(root_idx, i) : 0;
}

// ---------------------------------------------------------------------------
// agg[i, :] = bias[:]
// ---------------------------------------------------------------------------
__global__ void initb_k(float* __restrict__ agg, const float* __restrict__ b, int N) {
    long long idx = (long long)blockIdx.x * blockDim.x + threadIdx.x;
    if (idx >= (long long)N * 64) return;
    int i = (int)(idx >> 6);
    int c = (int)(idx & 63) * 4;
    *(float4*)(agg + (size_t)i * 256 + c) = *(const float4*)(b + c);
}

__global__ void zero_k(float* __restrict__ p, int n4) {
    int i = blockIdx.x * blockDim.x + threadIdx.x;
    if (i < n4) ((float4*)p)[i] = make_float4(0.f, 0.f, 0.f, 0.f);
}

// ---------------------------------------------------------------------------
// Edge scatter: agg[dst[e], :] += w[e] * H[src[e], :]
// ---------------------------------------------------------------------------
__global__ void scatter_k(const float* __restrict__ H,
                          const void* __restrict__ adjs, int E,
                          const float* __restrict__ w,
                          float* __restrict__ agg) {
    long long idx = (long long)blockIdx.x * blockDim.x + threadIdx.x;
    if (idx >= (long long)E * 64) return;
    int e  = (int)(idx >> 6);
    int c  = (int)(idx & 63) * 4;
    int s  = ldidx(adjs, e);
    int d  = ldidx(adjs, E + e);
    float wv = __ldg(&w[e]);
    float4 hv = *(const float4*)(H + (size_t)s * 256 + c);
    float* p = agg + (size_t)d * 256 + c;
    asm volatile("red.global.add.v4.f32 [%0], {%1,%2,%3,%4};"
                 :: "l"(p), "f"(wv * hv.x), "f"(wv * hv.y),
                    "f"(wv * hv.z), "f"(wv * hv.w)
                 : "memory");
}

// ---------------------------------------------------------------------------
// bf16 split + pre-swizzled (SW128) GMEM write, K=256 layout (for W only).
// ---------------------------------------------------------------------------
static __device__ __forceinline__ void write_split8(
    __nv_bfloat16* __restrict__ Ah, __nv_bfloat16* __restrict__ Al,
    int row, int k0, const float* v) {
    __align__(16) __nv_bfloat16 h[8], l[8];
#pragma unroll
    for (int j = 0; j < 8; j++) {
        float x = v[j];
        __nv_bfloat16 hi = __float2bfloat16(x);
        h[j] = hi;
        l[j] = __float2bfloat16(x - __bfloat162float(hi));
    }
    size_t off = (size_t)row * 512 + ((size_t)(k0 >> 6) << 7)
               + (size_t)(((k0 & 63) * 2) ^ ((row & 7) << 4));
    *(uint4*)((char*)Ah + off) = *(const uint4*)h;
    *(uint4*)((char*)Al + off) = *(const uint4*)l;
}

// W slice [off:off+256, 256] -> B[n,k] = W[off+k, n] split pre-swizzled
__global__ void convW_k(const float* __restrict__ W, int off,
                        __nv_bfloat16* __restrict__ Bh,
                        __nv_bfloat16* __restrict__ Bl) {
    int idx = blockIdx.x * blockDim.x + threadIdx.x;
    if (idx >= 256 * 32) return;
    int n  = idx >> 5;
    int k0 = (idx & 31) * 8;
    float v[8];
#pragma unroll
    for (int j = 0; j < 8; j++) v[j] = W[(size_t)(off + k0 + j) * 256 + n];
    write_split8(Bh, Bl, n, k0, v);
}

// Both halves of a [512,256] W in one launch
__global__ void convW2_k(const float* __restrict__ W,
                         __nv_bfloat16* __restrict__ Bh,  __nv_bfloat16* __restrict__ Bl,
                         __nv_bfloat16* __restrict__ B2h, __nv_bfloat16* __restrict__ B2l) {
    int idx = blockIdx.x * blockDim.x + threadIdx.x;
    if (idx >= 2 * 256 * 32) return;
    int half = idx >> 13;
    int id   = idx & 8191;
    int n  = id >> 5;
    int k0 = (id & 31) * 8;
    float v[8];
#pragma unroll
    for (int j = 0; j < 8; j++) v[j] = W[(size_t)(half * 256 + k0 + j) * 256 + n];
    if (half == 0) write_split8(Bh, Bl, n, k0, v);
    else           write_split8(B2h, B2l, n, k0, v);
}

// ---------------------------------------------------------------------------
// Fused GEMM: C[M,256] = split3_bf16( f(A[M,256]) ) @ W[256,256]
//   A is fp32; leakyA applies leaky before split; rowmap (optional) gathers
//   A rows (root-term). W pre-split as Bhi/Blo (pre-swizzled K-major).
// In-SMEM conversion: cp.async brings fp32 chunk (128 rows x 64 k = 32KB),
// threads stage 16 floats in regs, barrier, write hi/lo bf16 in place.
// atomic_out: K-split mode — grid = 4 CTAs, CTA j computes chunk j and
// red.global.add's into C (use with zeroed C).
// Epilogue (normal): C = acc (+ Radd[bmap[row]]) (+bias, leaky if epi).
// ---------------------------------------------------------------------------
constexpr int GEMM_STAGE_BYTES = 96 * 1024;   // A 32K (fp32->hi16K+lo16K) | Bh 32K | Bl 32K
constexpr int GEMM_SMEM = 2 * GEMM_STAGE_BYTES;

__global__ __launch_bounds__(512, 1)
void gemm_fA_k(const float* __restrict__ A,
               const int* __restrict__ rowmap, int leakyA,
               const __nv_bfloat16* __restrict__ Bhi,
               const __nv_bfloat16* __restrict__ Blo,
               float* __restrict__ C, int Mrows, int atomic_out,
               const float* __restrict__ Radd, const int* __restrict__ bmap,
               const float* __restrict__ bias, int epi) {
    extern __shared__ char smem[];
    const uint32_t smem_base = smem_to_u32(smem);
    const int tid  = threadIdx.x;
    const int wid  = tid >> 5;
    const int lane = tid & 31;

    const int m0 = atomic_out ? 0 : blockIdx.x * 128;
    const int cb = atomic_out ? blockIdx.x : 0;    // first chunk
    const int nch = atomic_out ? 1 : 4;

    const int wm32 = (wid & 3) * 32;
    const int wn64 = (wid >> 2) * 64;

    const char* bH = (const char*)Bhi;
    const char* bL = (const char*)Blo;

    auto copy_chunk = [&](int chunk, int s) {
        uint32_t sb = smem_base + s * GEMM_STAGE_BYTES;
        // A: fp32 rows, 64 floats (256B) per row
        for (int t = tid; t < 2048; t += 512) {
            int r = t >> 4, cB = (t & 15) << 4;
            int gr = m0 + r;
            bool ok = gr < Mrows;
            int srow = rowmap ? (ok ? rowmap[r] : 0) : (ok ? gr : 0);
            const char* src = (const char*)A + (size_t)srow * 1024
                            + (size_t)chunk * 256 + cB;
            cp16z(sb + r * 256 + cB, src, ok);
        }
        // B hi/lo: 256 rows x 128B, pre-swizzled
        size_t co = (size_t)chunk * 128;
        for (int t = tid; t < 2048; t += 512) {
            int r = t >> 3, cB = (t & 7) << 4;
            cp16(sb + 32768 + r * 128 + cB, bH + (size_t)r * 512 + co + cB);
        }
        for (int t = tid; t < 2048; t += 512) {
            int r = t >> 3, cB = (t & 7) << 4;
            cp16(sb + 65536 + r * 128 + cB, bL + (size_t)r * 512 + co + cB);
        }
        asm volatile("cp.async.commit_group;" ::: "memory");
    };

    // ldmatrix address constants (SW128 swizzle)
    const int lr = lane & 7;
    const int q  = lane >> 3;
    const uint32_t swz = (uint32_t)(lr << 4);
    const int a_row = wm32 + ((q & 1) << 3) + lr;
    const int a_kof = (q >> 1) << 3;
    const int b_row = wn64 + ((q >> 1) << 3) + lr;
    const int b_kof = (q & 1) << 3;

    float acc[16][4];
#pragma unroll
    for (int t = 0; t < 16; t++)
#pragma unroll
        for (int j = 0; j < 4; j++) acc[t][j] = 0.0f;

    copy_chunk(cb, 0);
    if (nch > 1) copy_chunk(cb + 1, 1);

    for (int i = 0; i < nch; i++) {
        const int s = i & 1;
        if (i + 1 < nch) asm volatile("cp.async.wait_group 1;" ::: "memory");
        else             asm volatile("cp.async.wait_group 0;" ::: "memory");
        __syncthreads();

        const uint32_t sA = smem_base + s * GEMM_STAGE_BYTES;
        const uint32_t sB = sA + 32768;

        // ---- In-place fp32 -> bf16 hi/lo split (swizzled) ----
        {
            float4 st[4];
#pragma unroll
            for (int u = 0; u < 4; u++) {
                int t = tid + u * 512;
                int r = t >> 4, cB = (t & 15) << 4;
                st[u] = *(const float4*)(smem + s * GEMM_STAGE_BYTES + r * 256 + cB);
            }
            __syncthreads();   // all fp32 reads done before overwrite
#pragma unroll
            for (int u = 0; u < 4; u++) {
                int t = tid + u * 512;
                int r = t >> 4, c4 = (t & 15) * 4;   // float index 0..60
                float v[4] = {st[u].x, st[u].y, st[u].z, st[u].w};
                if (leakyA) {
#pragma unroll
                    for (int j = 0; j < 4; j++) v[j] = leaky(v[j]);
                }
                __align__(8) __nv_bfloat16 h[4], l[4];
#pragma unroll
                for (int j = 0; j < 4; j++) {
                    __nv_bfloat16 hi = __float2bfloat16(v[j]);
                    h[j] = hi;
                    l[j] = __float2bfloat16(v[j] - __bfloat162float(hi));
                }
                uint32_t off = (uint32_t)(r * 128) + (uint32_t)((c4 * 2) ^ ((r & 7) << 4));
                *(uint64_t*)(smem + s * GEMM_STAGE_BYTES + off)         = *(const uint64_t*)h;
                *(uint64_t*)(smem + s * GEMM_STAGE_BYTES + 16384 + off) = *(const uint64_t*)l;
            }
        }
        __syncthreads();   // bf16 tiles visible

#pragma unroll
        for (int ks = 0; ks < 4; ks++) {
            uint32_t ah[2][4], al[2][4];
#pragma unroll
            for (int mt = 0; mt < 2; mt++) {
                uint32_t ra = sA + (uint32_t)((a_row + mt * 16) * 128)
                            + ((uint32_t)((a_kof + ks * 16) * 2) ^ swz);
                LDSM4(ah[mt], ra);
                LDSM4(al[mt], ra + 16384);
            }
#pragma unroll
            for (int np = 0; np < 4; np++) {
                uint32_t bh[4], bl2[4];
                uint32_t rb = sB + (uint32_t)((b_row + np * 16) * 128)
                            + ((uint32_t)((b_kof + ks * 16) * 2) ^ swz);
                LDSM4(bh, rb);
                LDSM4(bl2, rb + 32768);
#pragma unroll
                for (int mt = 0; mt < 2; mt++) {
#pragma unroll
                    for (int sub = 0; sub < 2; sub++) {
                        float* c = acc[mt * 8 + np * 2 + sub];
                        MMA_BF16(c, ah[mt], bh[2 * sub], bh[2 * sub + 1]);
                        MMA_BF16(c, ah[mt], bl2[2 * sub], bl2[2 * sub + 1]);
                        MMA_BF16(c, al[mt], bh[2 * sub], bh[2 * sub + 1]);
                    }
                }
            }
        }
        __syncthreads();               // stage s free for next copy
        if (i + 2 < nch) copy_chunk(cb + i + 2, s);
    }

    // ---- Epilogue ----
    const int gr = lane >> 2;
    const int gc = (lane & 3) * 2;
#pragma unroll
    for (int mt = 0; mt < 2; mt++) {
        int row0 = m0 + wm32 + mt * 16 + gr;
        int row8 = row0 + 8;
        const float* R0 = nullptr;
        const float* R8 = nullptr;
        if (Radd) {
            if (row0 < Mrows) R0 = Radd + (size_t)bmap[row0] * 256;
            if (row8 < Mrows) R8 = Radd + (size_t)bmap[row8] * 256;
        }
#pragma unroll
        for (int np = 0; np < 4; np++) {
#pragma unroll
            for (int sub = 0; sub < 2; sub++) {
                const float* c = acc[mt * 8 + np * 2 + sub];
                int col = wn64 + np * 16 + sub * 8 + gc;
                if (atomic_out) {
                    if (row0 < Mrows) {
                        float* p = C + (size_t)row0 * 256 + col;
                        asm volatile("red.global.add.f32 [%0], %1;" :: "l"(p), "f"(c[0]) : "memory");
                        asm volatile("red.global.add.f32 [%0], %1;" :: "l"(p + 1), "f"(c[1]) : "memory");
                    }
                    if (row8 < Mrows) {
                        float* p = C + (size_t)row8 * 256 + col;
                        asm volatile("red.global.add.f32 [%0], %1;" :: "l"(p), "f"(c[2]) : "memory");
                        asm volatile("red.global.add.f32 [%0], %1;" :: "l"(p + 1), "f"(c[3]) : "memory");
                    }
                    continue;
                }
                float b0 = 0.f, b1 = 0.f;
                if (epi) { b0 = bias[col]; b1 = bias[col + 1]; }
                if (row0 < Mrows) {
                    float2 v = make_float2(c[0], c[1]);
                    if (R0) { v.x += R0[col]; v.y += R0[col + 1]; }
                    if (epi) { v.x = leaky(v.x + b0); v.y = leaky(v.y + b1); }
                    *(float2*)(C + (size_t)row0 * 256 + col) = v;
                }
                if (row8 < Mrows) {
                    float2 v = make_float2(c[2], c[3]);
                    if (R8) { v.x += R8[col]; v.y += R8[col + 1]; }
                    if (epi) { v.x = leaky(v.x + b0); v.y = leaky(v.y + b1); }
                    *(float2*)(C + (size_t)row8 * 256 + col) = v;
                }
            }
        }
    }
}

// ---------------------------------------------------------------------------
extern "C" void kernel_launch(void* const* d_in, const int* in_sizes, int n_in,
                              void* d_out, int out_size) {
    const float* features = (const float*)d_in[0];   // [N,256]
    const float* values   = (const float*)d_in[1];   // [E]
    const float* W1       = (const float*)d_in[2];   // [256,256]
    const float* b1       = (const float*)d_in[3];   // [256]
    const float* W2       = (const float*)d_in[4];   // [512,256]
    const float* b2       = (const float*)d_in[5];   // [256]
    const float* Wl       = (const float*)d_in[6];   // [512,256]
    const float* bl       = (const float*)d_in[7];   // [256]
    const void*  adjs     = d_in[8];                 // [2,E]
    const void*  batch    = d_in[9];                 // [N]
    const void*  root_idx = d_in[10];                // [B]

    const int N = in_sizes[0] / 256;
    const int E = in_sizes[8] / 2;
    const int B = in_sizes[10];
    const int ntiles = (N + 127) / 128;

    __nv_bfloat16 *Bh, *Bl, *B2h, *B2l;
    float *H, *AGG1, *AGG2, *R;
    int *batch32, *rootidx32;
    cudaGetSymbolAddress((void**)&Bh,       g_Bhi);
    cudaGetSymbolAddress((void**)&Bl,       g_Blo);
    cudaGetSymbolAddress((void**)&B2h,      g_B2hi);
    cudaGetSymbolAddress((void**)&B2l,      g_B2lo);
    cudaGetSymbolAddress((void**)&R,        g_R);
    cudaGetSymbolAddress((void**)&H,        g_H);
    cudaGetSymbolAddress((void**)&AGG1,     g_AGG1);
    cudaGetSymbolAddress((void**)&AGG2,     g_AGG2);
    cudaGetSymbolAddress((void**)&batch32,  g_batch32);
    cudaGetSymbolAddress((void**)&rootidx32,g_rootidx32);

    cudaFuncSetAttribute(gemm_fA_k, cudaFuncAttributeMaxDynamicSharedMemorySize, GEMM_SMEM);

    float* out = (float*)d_out;
    const int T = 256;
    long long nwork = (long long)N * 64;
    long long ework = (long long)E * 64;
    int nblocks = (int)((nwork + T - 1) / T);
    int eblocks = (int)((ework + T - 1) / T);
    int convW_blocks  = (256 * 32 + T - 1) / T;
    int convW2_blocks = (2 * 256 * 32 + T - 1) / T;

    detect_k<<<1, 256>>>(adjs);
    root_k<<<(N + T - 1) / T, T>>>(batch, root_idx, batch32, rootidx32, N, B);

    // --- conv1: H1 = features @ W1 ---
    convW_k<<<convW_blocks, T>>>(W1, 0, Bh, Bl);
    initb_k<<<nblocks, T>>>(AGG1, b1, N);
    gemm_fA_k<<<ntiles, 512, GEMM_SMEM>>>(features, nullptr, 0, Bh, Bl, H, N, 0,
                                          nullptr, nullptr, nullptr, 0);
    scatter_k<<<eblocks, T>>>(H, adjs, E, values, AGG1);

    // --- conv2: H2 = leaky(AGG1) @ W2_top + leaky(f1[root]) @ W2_bot ---
    convW2_k<<<convW2_blocks, T>>>(W2, Bh, Bl, B2h, B2l);
    zero_k<<<32, 256>>>(R, BMAX * 64);
    gemm_fA_k<<<4, 512, GEMM_SMEM>>>(features, rootidx32, 1, B2h, B2l, R, B, 1,
                                     nullptr, nullptr, nullptr, 0);
    initb_k<<<nblocks, T>>>(AGG2, b2, N);
    gemm_fA_k<<<ntiles, 512, GEMM_SMEM>>>(AGG1, nullptr, 1, Bh, Bl, H, N, 0,
                                          R, batch32, nullptr, 0);
    scatter_k<<<eblocks, T>>>(H, adjs, E, values, AGG2);

    // --- final: out = leaky(leaky(AGG2) @ Wl_top + AGG1[root] @ Wl_bot + bl) ---
    convW2_k<<<convW2_blocks, T>>>(Wl, Bh, Bl, B2h, B2l);
    zero_k<<<32, 256>>>(R, BMAX * 64);
    gemm_fA_k<<<4, 512, GEMM_SMEM>>>(AGG1, rootidx32, 0, B2h, B2l, R, B, 1,
                                     nullptr, nullptr, nullptr, 0);
    gemm_fA_k<<<ntiles, 512, GEMM_SMEM>>>(AGG2, nullptr, 1, Bh, Bl, out, N, 0,
                                          R, batch32, bl, 1);
}